// round 1
// baseline (speedup 1.0000x reference)
#include <cuda_runtime.h>
#include <cuda_bf16.h>
#include <cstdint>

// Problem constants
#define BB 4
#define LL 1024
#define DD 768
#define HH 12
#define NEE 42
#define MM 8
#define ST (NEE*NEE)   // 1764

// Scratch (device globals; no allocation allowed)
__device__ float g_ent_att[BB*HH*NEE*LL];   // [b][h][e][l]
__device__ float g_W[BB*ST*LL];             // [b][s*42+t][l]  (pre-normalization, includes 1/H)
__device__ float g_Z[BB*ST];                // row sums of g_W

// ---------------- packed f32x2 helpers ----------------
__device__ __forceinline__ unsigned long long pack2(float x, float y) {
    unsigned long long r;
    asm("mov.b64 %0, {%1, %2};" : "=l"(r) : "f"(x), "f"(y));
    return r;
}
__device__ __forceinline__ void unpack2(unsigned long long v, float& x, float& y) {
    asm("mov.b64 {%0, %1}, %2;" : "=f"(x), "=f"(y) : "l"(v));
}
__device__ __forceinline__ unsigned long long ffma2(unsigned long long a,
                                                    unsigned long long b,
                                                    unsigned long long c) {
    unsigned long long d;
    asm("fma.rn.f32x2 %0, %1, %2, %3;" : "=l"(d) : "l"(a), "l"(b), "l"(c));
    return d;
}

// ---------------- Kernel A: ent_att = mean over valid mentions of attention rows ----------------
// grid: B*H*NE blocks, 256 threads
__global__ void __launch_bounds__(256) ent_att_kernel(const float* __restrict__ att,
                                                      const int* __restrict__ midx,
                                                      const int* __restrict__ mmask) {
    int blk = blockIdx.x;              // b*H*NE + h*NE + e
    int e = blk % NEE;
    int h = (blk / NEE) % HH;
    int b = blk / (NEE * HH);

    const int* ip = midx  + (b*NEE + e)*MM;
    const int* mp = mmask + (b*NEE + e)*MM;
    int   idx[MM];
    float val[MM];
    int cnt = 0;
#pragma unroll
    for (int m = 0; m < MM; m++) {
        int i = ip[m] + 1;                       // OFFSET
        bool v = (mp[m] > 0) && (i < LL);
        idx[m] = v ? i : 0;
        val[m] = v ? 1.0f : 0.0f;
        cnt += v ? 1 : 0;
    }
    float inv = 1.0f / (float)(cnt > 0 ? cnt : 1);

    const float* abase = att + ((size_t)(b*HH + h)) * LL * LL;
    float* out = g_ent_att + (size_t)blk * LL;
    for (int l = threadIdx.x; l < LL; l += blockDim.x) {
        float s = 0.0f;
#pragma unroll
        for (int m = 0; m < MM; m++)
            s = fmaf(val[m], abase[(size_t)idx[m]*LL + l], s);
        out[l] = s * inv;
    }
}

// ---------------- Kernel B: W[b,s,t,l] = (1/H) sum_h A[h,s,l]*A[h,t,l] ----------------
// l tiled by 16 -> static smem 12*42*16*4 = 32256 B
#define TL 16
__global__ void __launch_bounds__(256) htatt_kernel() {
    __shared__ float As[HH*NEE*TL];
    int b  = blockIdx.y;
    int l0 = blockIdx.x * TL;

    const float* src = g_ent_att + (size_t)b * HH * NEE * LL;
    for (int j = threadIdx.x; j < HH*NEE*TL; j += blockDim.x) {
        int r = j >> 4;      // 0..503  (h*42+e)
        int i = j & 15;      // l offset
        As[j] = src[(size_t)r*LL + l0 + i];
    }
    __syncthreads();

    int lane = threadIdx.x & 15;   // l within tile
    int grp  = threadIdx.x >> 4;   // 0..15 (t-stride group)
    float* Wout = g_W + (size_t)b * ST * LL;
    const float invH = 1.0f / (float)HH;

    for (int s = 0; s < NEE; s++) {
        float as[HH];
#pragma unroll
        for (int h = 0; h < HH; h++)
            as[h] = As[(h*NEE + s)*TL + lane];
        for (int t = grp; t < NEE; t += 16) {
            float acc = 0.0f;
#pragma unroll
            for (int h = 0; h < HH; h++)
                acc = fmaf(as[h], As[(h*NEE + t)*TL + lane], acc);
            Wout[(size_t)(s*NEE + t)*LL + l0 + lane] = acc * invH;
        }
    }
}

// ---------------- Kernel B2: Z[b,st] = sum_l W ----------------
// grid: B*ST blocks, 256 threads
__global__ void __launch_bounds__(256) rowsum_kernel() {
    int row = blockIdx.x;                 // b*ST + p
    const float* w = g_W + (size_t)row * LL;
    float s = 0.0f;
    for (int i = threadIdx.x; i < LL; i += 256) s += w[i];
#pragma unroll
    for (int off = 16; off > 0; off >>= 1)
        s += __shfl_down_sync(0xffffffffu, s, off);
    __shared__ float red[8];
    int lane = threadIdx.x & 31, warp = threadIdx.x >> 5;
    if (lane == 0) red[warp] = s;
    __syncthreads();
    if (threadIdx.x == 0) {
        float t = 0.0f;
#pragma unroll
        for (int i = 0; i < 8; i++) t += red[i];
        g_Z[row] = t;
    }
}

// ---------------- Kernel C: feature_map = rowscale * (W @ seq) ----------------
// per batch: M=1764, N=768, K=1024. 64x64 tile, BK=16, 128 threads, 8x4 per thread (f32x2)
#define BM 64
#define BN 64
#define BK 16
__global__ void __launch_bounds__(128) gemm_kernel(const float* __restrict__ seq,
                                                   float* __restrict__ out) {
    int b  = blockIdx.z;
    int m0 = blockIdx.y * BM;
    int n0 = blockIdx.x * BN;

    const float* A  = g_W + (size_t)b * ST * LL;     // [M,K] row-major
    const float* Bm = seq + (size_t)b * LL * DD;     // [K,N] row-major
    float*       C  = out + (size_t)b * ST * DD;     // [M,N] row-major

    __shared__ float As[BK][BM];   // transposed A tile
    __shared__ float Bs[BK][BN];

    int tid = threadIdx.x;
    int tx = tid & 15;     // n-group (4 cols)
    int ty = tid >> 4;     // m-group (8 rows)

    unsigned long long acc[4][4];
#pragma unroll
    for (int i = 0; i < 4; i++)
#pragma unroll
        for (int j = 0; j < 4; j++) acc[i][j] = pack2(0.0f, 0.0f);

    for (int k0 = 0; k0 < LL; k0 += BK) {
        // load A tile (transpose into smem)
#pragma unroll
        for (int it = 0; it < 2; it++) {
            int fi  = tid + it*128;      // 0..255
            int row = fi >> 2;           // 0..63
            int c4  = fi & 3;            // 0..3
            float4 v = make_float4(0.f, 0.f, 0.f, 0.f);
            int gr = m0 + row;
            if (gr < ST)
                v = *(const float4*)(A + (size_t)gr*LL + k0 + c4*4);
            As[c4*4 + 0][row] = v.x;
            As[c4*4 + 1][row] = v.y;
            As[c4*4 + 2][row] = v.z;
            As[c4*4 + 3][row] = v.w;
        }
        // load B tile
#pragma unroll
        for (int it = 0; it < 2; it++) {
            int fi = tid + it*128;
            int r  = fi >> 4;            // 0..15
            int c4 = fi & 15;            // 0..15
            *(float4*)(&Bs[r][c4*4]) =
                *(const float4*)(Bm + (size_t)(k0 + r)*DD + n0 + c4*4);
        }
        __syncthreads();

#pragma unroll
        for (int k = 0; k < BK; k++) {
            float4 a0 = *(const float4*)(&As[k][ty*8]);
            float4 a1 = *(const float4*)(&As[k][ty*8 + 4]);
            float4 bv = *(const float4*)(&Bs[k][tx*4]);
            unsigned long long ap[4];
            ap[0] = pack2(a0.x, a0.y);
            ap[1] = pack2(a0.z, a0.w);
            ap[2] = pack2(a1.x, a1.y);
            ap[3] = pack2(a1.z, a1.w);
            float bj[4] = {bv.x, bv.y, bv.z, bv.w};
#pragma unroll
            for (int j = 0; j < 4; j++) {
                unsigned long long bb = pack2(bj[j], bj[j]);
                acc[0][j] = ffma2(ap[0], bb, acc[0][j]);
                acc[1][j] = ffma2(ap[1], bb, acc[1][j]);
                acc[2][j] = ffma2(ap[2], bb, acc[2][j]);
                acc[3][j] = ffma2(ap[3], bb, acc[3][j]);
            }
        }
        __syncthreads();
    }

    // epilogue: scale each row by 1/(Z+1e-5), store
#pragma unroll
    for (int i = 0; i < 4; i++) {
        int mlo = m0 + ty*8 + 2*i;       // even row of the pair
#pragma unroll
        for (int half = 0; half < 2; half++) {
            int gm = mlo + half;
            if (gm < ST) {
                float scale = 1.0f / (g_Z[b*ST + gm] + 1e-5f);
                float4 o;
                float x0, x1;
                unpack2(acc[i][0], x0, x1); o.x = (half ? x1 : x0) * scale;
                unpack2(acc[i][1], x0, x1); o.y = (half ? x1 : x0) * scale;
                unpack2(acc[i][2], x0, x1); o.z = (half ? x1 : x0) * scale;
                unpack2(acc[i][3], x0, x1); o.w = (half ? x1 : x0) * scale;
                *(float4*)(C + (size_t)gm*DD + n0 + tx*4) = o;
            }
        }
    }
}

// ---------------- launch ----------------
extern "C" void kernel_launch(void* const* d_in, const int* in_sizes, int n_in,
                              void* d_out, int out_size) {
    const float* seq   = (const float*)d_in[0];   // [4,1024,768]
    const float* att   = (const float*)d_in[1];   // [4,12,1024,1024]
    const int*   midx  = (const int*)  d_in[2];   // [4,42,8]
    const int*   mmask = (const int*)  d_in[3];   // [4,42,8]
    float*       out   = (float*)d_out;           // [4,42,42,768]

    ent_att_kernel<<<BB*HH*NEE, 256>>>(att, midx, mmask);
    htatt_kernel<<<dim3(LL/TL, BB), 256>>>();
    rowsum_kernel<<<BB*ST, 256>>>();
    gemm_kernel<<<dim3(DD/BN, (ST + BM - 1)/BM, BB), 128>>>(seq, out);
}

// round 2
// speedup vs baseline: 1.0061x; 1.0061x over previous
#include <cuda_runtime.h>
#include <cuda_bf16.h>
#include <cstdint>

// Problem constants
#define BB 4
#define LL 1024
#define DD 768
#define HH 12
#define NEE 42
#define MM 8
#define ST (NEE*NEE)   // 1764

// Scratch (device globals; no allocation allowed)
__device__ float g_ent_att[BB*HH*NEE*LL];   // [b][h][e][l]
__device__ float g_W[BB*ST*LL];             // [b][s*42+t][l]  (pre-normalization, includes 1/H)
__device__ float g_Z[BB*ST];                // row sums of g_W

// ---------------- packed f32x2 helpers ----------------
__device__ __forceinline__ unsigned long long pack2(float x, float y) {
    unsigned long long r;
    asm("mov.b64 %0, {%1, %2};" : "=l"(r) : "f"(x), "f"(y));
    return r;
}
__device__ __forceinline__ void unpack2(unsigned long long v, float& x, float& y) {
    asm("mov.b64 {%0, %1}, %2;" : "=f"(x), "=f"(y) : "l"(v));
}
__device__ __forceinline__ unsigned long long ffma2(unsigned long long a,
                                                    unsigned long long b,
                                                    unsigned long long c) {
    unsigned long long d;
    asm("fma.rn.f32x2 %0, %1, %2, %3;" : "=l"(d) : "l"(a), "l"(b), "l"(c));
    return d;
}

// ---------------- Kernel A: ent_att = mean over valid mentions of attention rows ----------------
// grid: B*H*NE blocks, 256 threads
__global__ void __launch_bounds__(256) ent_att_kernel(const float* __restrict__ att,
                                                      const int* __restrict__ midx,
                                                      const int* __restrict__ mmask) {
    int blk = blockIdx.x;              // b*H*NE + h*NE + e
    int e = blk % NEE;
    int h = (blk / NEE) % HH;
    int b = blk / (NEE * HH);

    const int* ip = midx  + (b*NEE + e)*MM;
    const int* mp = mmask + (b*NEE + e)*MM;
    int   idx[MM];
    float val[MM];
    int cnt = 0;
#pragma unroll
    for (int m = 0; m < MM; m++) {
        int i = ip[m] + 1;                       // OFFSET
        bool v = (mp[m] > 0) && (i < LL);
        idx[m] = v ? i : 0;
        val[m] = v ? 1.0f : 0.0f;
        cnt += v ? 1 : 0;
    }
    float inv = 1.0f / (float)(cnt > 0 ? cnt : 1);

    const float* abase = att + ((size_t)(b*HH + h)) * LL * LL;
    float* out = g_ent_att + (size_t)blk * LL;
    for (int l = threadIdx.x; l < LL; l += blockDim.x) {
        float s = 0.0f;
#pragma unroll
        for (int m = 0; m < MM; m++)
            s = fmaf(val[m], abase[(size_t)idx[m]*LL + l], s);
        out[l] = s * inv;
    }
}

// ---------------- Kernel B: W[b,s,t,l] = (1/H) sum_h A[h,s,l]*A[h,t,l] ----------------
// l tiled by 16 -> static smem 12*42*16*4 = 32256 B
#define TL 16
__global__ void __launch_bounds__(256) htatt_kernel() {
    __shared__ float As[HH*NEE*TL];
    int b  = blockIdx.y;
    int l0 = blockIdx.x * TL;

    const float* src = g_ent_att + (size_t)b * HH * NEE * LL;
    for (int j = threadIdx.x; j < HH*NEE*TL; j += blockDim.x) {
        int r = j >> 4;      // 0..503  (h*42+e)
        int i = j & 15;      // l offset
        As[j] = src[(size_t)r*LL + l0 + i];
    }
    __syncthreads();

    int lane = threadIdx.x & 15;   // l within tile
    int grp  = threadIdx.x >> 4;   // 0..15 (t-stride group)
    float* Wout = g_W + (size_t)b * ST * LL;
    const float invH = 1.0f / (float)HH;

    for (int s = 0; s < NEE; s++) {
        float as[HH];
#pragma unroll
        for (int h = 0; h < HH; h++)
            as[h] = As[(h*NEE + s)*TL + lane];
        for (int t = grp; t < NEE; t += 16) {
            float acc = 0.0f;
#pragma unroll
            for (int h = 0; h < HH; h++)
                acc = fmaf(as[h], As[(h*NEE + t)*TL + lane], acc);
            Wout[(size_t)(s*NEE + t)*LL + l0 + lane] = acc * invH;
        }
    }
}

// ---------------- Kernel B2: Z[b,st] = sum_l W ----------------
// grid: B*ST blocks, 256 threads
__global__ void __launch_bounds__(256) rowsum_kernel() {
    int row = blockIdx.x;                 // b*ST + p
    const float* w = g_W + (size_t)row * LL;
    float s = 0.0f;
    for (int i = threadIdx.x; i < LL; i += 256) s += w[i];
#pragma unroll
    for (int off = 16; off > 0; off >>= 1)
        s += __shfl_down_sync(0xffffffffu, s, off);
    __shared__ float red[8];
    int lane = threadIdx.x & 31, warp = threadIdx.x >> 5;
    if (lane == 0) red[warp] = s;
    __syncthreads();
    if (threadIdx.x == 0) {
        float t = 0.0f;
#pragma unroll
        for (int i = 0; i < 8; i++) t += red[i];
        g_Z[row] = t;
    }
}

// ---------------- Kernel C: feature_map = rowscale * (W @ seq) ----------------
// per batch: M=1764, N=768, K=1024. 64x64 tile, BK=16, 128 threads, 8x4 per thread (f32x2)
#define BM 64
#define BN 64
#define BK 16
__global__ void __launch_bounds__(128) gemm_kernel(const float* __restrict__ seq,
                                                   float* __restrict__ out) {
    int b  = blockIdx.z;
    int m0 = blockIdx.y * BM;
    int n0 = blockIdx.x * BN;

    const float* A  = g_W + (size_t)b * ST * LL;     // [M,K] row-major
    const float* Bm = seq + (size_t)b * LL * DD;     // [K,N] row-major
    float*       C  = out + (size_t)b * ST * DD;     // [M,N] row-major

    __shared__ float As[BK][BM];   // transposed A tile
    __shared__ float Bs[BK][BN];

    int tid = threadIdx.x;
    int tx = tid & 15;     // n-group (4 cols)
    int ty = tid >> 4;     // m-group (8 rows)

    unsigned long long acc[4][4];
#pragma unroll
    for (int i = 0; i < 4; i++)
#pragma unroll
        for (int j = 0; j < 4; j++) acc[i][j] = pack2(0.0f, 0.0f);

    for (int k0 = 0; k0 < LL; k0 += BK) {
        // load A tile (transpose into smem)
#pragma unroll
        for (int it = 0; it < 2; it++) {
            int fi  = tid + it*128;      // 0..255
            int row = fi >> 2;           // 0..63
            int c4  = fi & 3;            // 0..3
            float4 v = make_float4(0.f, 0.f, 0.f, 0.f);
            int gr = m0 + row;
            if (gr < ST)
                v = *(const float4*)(A + (size_t)gr*LL + k0 + c4*4);
            As[c4*4 + 0][row] = v.x;
            As[c4*4 + 1][row] = v.y;
            As[c4*4 + 2][row] = v.z;
            As[c4*4 + 3][row] = v.w;
        }
        // load B tile
#pragma unroll
        for (int it = 0; it < 2; it++) {
            int fi = tid + it*128;
            int r  = fi >> 4;            // 0..15
            int c4 = fi & 15;            // 0..15
            *(float4*)(&Bs[r][c4*4]) =
                *(const float4*)(Bm + (size_t)(k0 + r)*DD + n0 + c4*4);
        }
        __syncthreads();

#pragma unroll
        for (int k = 0; k < BK; k++) {
            float4 a0 = *(const float4*)(&As[k][ty*8]);
            float4 a1 = *(const float4*)(&As[k][ty*8 + 4]);
            float4 bv = *(const float4*)(&Bs[k][tx*4]);
            unsigned long long ap[4];
            ap[0] = pack2(a0.x, a0.y);
            ap[1] = pack2(a0.z, a0.w);
            ap[2] = pack2(a1.x, a1.y);
            ap[3] = pack2(a1.z, a1.w);
            float bj[4] = {bv.x, bv.y, bv.z, bv.w};
#pragma unroll
            for (int j = 0; j < 4; j++) {
                unsigned long long bb = pack2(bj[j], bj[j]);
                acc[0][j] = ffma2(ap[0], bb, acc[0][j]);
                acc[1][j] = ffma2(ap[1], bb, acc[1][j]);
                acc[2][j] = ffma2(ap[2], bb, acc[2][j]);
                acc[3][j] = ffma2(ap[3], bb, acc[3][j]);
            }
        }
        __syncthreads();
    }

    // epilogue: scale each row by 1/(Z+1e-5), store
#pragma unroll
    for (int i = 0; i < 4; i++) {
        int mlo = m0 + ty*8 + 2*i;       // even row of the pair
#pragma unroll
        for (int half = 0; half < 2; half++) {
            int gm = mlo + half;
            if (gm < ST) {
                float scale = 1.0f / (g_Z[b*ST + gm] + 1e-5f);
                float4 o;
                float x0, x1;
                unpack2(acc[i][0], x0, x1); o.x = (half ? x1 : x0) * scale;
                unpack2(acc[i][1], x0, x1); o.y = (half ? x1 : x0) * scale;
                unpack2(acc[i][2], x0, x1); o.z = (half ? x1 : x0) * scale;
                unpack2(acc[i][3], x0, x1); o.w = (half ? x1 : x0) * scale;
                *(float4*)(C + (size_t)gm*DD + n0 + tx*4) = o;
            }
        }
    }
}

// ---------------- launch ----------------
extern "C" void kernel_launch(void* const* d_in, const int* in_sizes, int n_in,
                              void* d_out, int out_size) {
    const float* seq   = (const float*)d_in[0];   // [4,1024,768]
    const float* att   = (const float*)d_in[1];   // [4,12,1024,1024]
    const int*   midx  = (const int*)  d_in[2];   // [4,42,8]
    const int*   mmask = (const int*)  d_in[3];   // [4,42,8]
    float*       out   = (float*)d_out;           // [4,42,42,768]

    ent_att_kernel<<<BB*HH*NEE, 256>>>(att, midx, mmask);
    htatt_kernel<<<dim3(LL/TL, BB), 256>>>();
    rowsum_kernel<<<BB*ST, 256>>>();
    gemm_kernel<<<dim3(DD/BN, (ST + BM - 1)/BM, BB), 128>>>(seq, out);
}

// round 4
// speedup vs baseline: 2.2754x; 2.2615x over previous
#include <cuda_runtime.h>
#include <cuda_bf16.h>
#include <cstdint>

// ---------------- problem constants ----------------
#define BB 4
#define LL 1024
#define DD 768
#define HH 12
#define NEE 42
#define MM 8
#define ST (NEE*NEE)     // 1764
#define NPAIR 903        // pairs with s<=t
#define PACK 1024        // padded packed rows (8 x 128)

// ---------------- device scratch ----------------
__device__ float         g_ent_att[BB*HH*NEE*LL];     // [b][h][e][l]
__device__ __nv_bfloat16 g_Whi[(size_t)BB*PACK*LL];   // packed symmetric W hi
__device__ __nv_bfloat16 g_Wlo[(size_t)BB*PACK*LL];   // packed symmetric W lo
__device__ __nv_bfloat16 g_BThi[(size_t)BB*DD*LL];    // seq^T hi [b][d][l]
__device__ __nv_bfloat16 g_BTlo[(size_t)BB*DD*LL];
__device__ float         g_Z[BB*PACK];                // packed row sums
__device__ int           g_ps[PACK];                  // packed row -> s
__device__ int           g_pt[PACK];                  // packed row -> t

// ---------------- PTX helpers ----------------
__device__ __forceinline__ uint32_t smem_u32(const void* p) {
    uint32_t a;
    asm("{ .reg .u64 t; cvta.to.shared.u64 t, %1; cvt.u32.u64 %0, t; }" : "=r"(a) : "l"(p));
    return a;
}
__device__ __forceinline__ void cp16(uint32_t dst, const void* src) {
    asm volatile("cp.async.cg.shared.global [%0], [%1], 16;" :: "r"(dst), "l"(src));
}
#define CP_COMMIT() asm volatile("cp.async.commit_group;" ::: "memory")
#define CP_WAIT1()  asm volatile("cp.async.wait_group 1;" ::: "memory")
#define CP_WAIT0()  asm volatile("cp.async.wait_group 0;" ::: "memory")

__device__ __forceinline__ void ldsm4(uint32_t& r0, uint32_t& r1, uint32_t& r2, uint32_t& r3,
                                      uint32_t addr) {
    asm volatile("ldmatrix.sync.aligned.m8n8.x4.shared.b16 {%0,%1,%2,%3}, [%4];"
                 : "=r"(r0), "=r"(r1), "=r"(r2), "=r"(r3) : "r"(addr));
}
__device__ __forceinline__ void mma16816(float* d, const uint32_t* a, const uint32_t* b) {
    asm volatile(
        "mma.sync.aligned.m16n8k16.row.col.f32.bf16.bf16.f32 "
        "{%0,%1,%2,%3},{%4,%5,%6,%7},{%8,%9},{%0,%1,%2,%3};"
        : "+f"(d[0]), "+f"(d[1]), "+f"(d[2]), "+f"(d[3])
        : "r"(a[0]), "r"(a[1]), "r"(a[2]), "r"(a[3]), "r"(b[0]), "r"(b[1]));
}

// ---------------- Kernel P: pair tables ----------------
__global__ void init_pairs() {
    int i = blockIdx.x * blockDim.x + threadIdx.x;
    if (i < ST) {
        int s = i / NEE, t = i % NEE;
        if (s <= t) {
            int r = s*NEE - s*(s+1)/2 + t;
            g_ps[r] = s; g_pt[r] = t;
        }
    }
}

// ---------------- Kernel A: ent_att ----------------
__global__ void __launch_bounds__(256) ent_att_kernel(const float* __restrict__ att,
                                                      const int* __restrict__ midx,
                                                      const int* __restrict__ mmask) {
    int blk = blockIdx.x;              // b*H*NE + h*NE + e
    int e = blk % NEE;
    int b = blk / (NEE * HH);

    const int* ip = midx  + (b*NEE + e)*MM;
    const int* mp = mmask + (b*NEE + e)*MM;
    int   idx[MM];
    float val[MM];
    int cnt = 0;
#pragma unroll
    for (int m = 0; m < MM; m++) {
        int i = ip[m] + 1;
        bool v = (mp[m] > 0) && (i < LL);
        idx[m] = v ? i : 0;
        val[m] = v ? 1.0f : 0.0f;
        cnt += v ? 1 : 0;
    }
    float inv = 1.0f / (float)(cnt > 0 ? cnt : 1);

    int h = (blk / NEE) % HH;
    const float* abase = att + ((size_t)(b*HH + h)) * LL * LL;
    float* out = g_ent_att + (size_t)blk * LL;
    for (int l = threadIdx.x; l < LL; l += blockDim.x) {
        float s = 0.0f;
#pragma unroll
        for (int m = 0; m < MM; m++)
            s = fmaf(val[m], abase[(size_t)idx[m]*LL + l], s);
        out[l] = s * inv;
    }
}

// ---------------- Kernel T: transpose+split seq -> BT hi/lo ----------------
__global__ void __launch_bounds__(256) transpose_conv(const float* __restrict__ seq) {
    __shared__ float t[32][33];
    int b = blockIdx.z;
    int l0 = blockIdx.x * 32, d0 = blockIdx.y * 32;
    int tx = threadIdx.x & 31, ty = threadIdx.x >> 5;
#pragma unroll
    for (int j = ty; j < 32; j += 8)
        t[j][tx] = seq[((size_t)b*LL + l0 + j)*DD + d0 + tx];
    __syncthreads();
#pragma unroll
    for (int j = ty; j < 32; j += 8) {
        float v = t[tx][j];
        __nv_bfloat16 hi = __float2bfloat16(v);
        float lo = v - __bfloat162float(hi);
        size_t o = ((size_t)b*DD + d0 + j)*LL + l0 + tx;
        g_BThi[o] = hi;
        g_BTlo[o] = __float2bfloat16(lo);
    }
}

// ---------------- Kernel B: W packed (s<=t), split to bf16 hi/lo ----------------
#define TL 16
__global__ void __launch_bounds__(256) htatt_kernel() {
    __shared__ float As[HH*NEE*TL];
    int b  = blockIdx.y;
    int l0 = blockIdx.x * TL;

    const float* src = g_ent_att + (size_t)b * HH * NEE * LL;
    for (int j = threadIdx.x; j < HH*NEE*TL; j += blockDim.x) {
        int r = j >> 4;
        int i = j & 15;
        As[j] = src[(size_t)r*LL + l0 + i];
    }
    __syncthreads();

    int lane = threadIdx.x & 15;
    int grp  = threadIdx.x >> 4;
    const float invH = 1.0f / (float)HH;

    for (int s = 0; s < NEE; s++) {
        float as[HH];
#pragma unroll
        for (int h = 0; h < HH; h++)
            as[h] = As[(h*NEE + s)*TL + lane];
        int rbase = s*NEE - s*(s+1)/2;
        for (int t = s + grp; t < NEE; t += 16) {
            float acc = 0.0f;
#pragma unroll
            for (int h = 0; h < HH; h++)
                acc = fmaf(as[h], As[(h*NEE + t)*TL + lane], acc);
            float w = acc * invH;
            __nv_bfloat16 hi = __float2bfloat16(w);
            float lo = w - __bfloat162float(hi);
            size_t o = ((size_t)b*PACK + rbase + t)*LL + l0 + lane;
            g_Whi[o] = hi;
            g_Wlo[o] = __float2bfloat16(lo);
        }
    }
}

// ---------------- Kernel B2: Z over packed rows ----------------
__global__ void __launch_bounds__(256) rowsum_kernel() {
    int blk = blockIdx.x;                 // b*NPAIR + r
    int b = blk / NPAIR, r = blk % NPAIR;
    const __nv_bfloat16* hi = g_Whi + ((size_t)b*PACK + r)*LL;
    const __nv_bfloat16* lo = g_Wlo + ((size_t)b*PACK + r)*LL;
    float s = 0.0f;
    for (int i = threadIdx.x; i < LL; i += 256)
        s += __bfloat162float(hi[i]) + __bfloat162float(lo[i]);
#pragma unroll
    for (int off = 16; off > 0; off >>= 1)
        s += __shfl_down_sync(0xffffffffu, s, off);
    __shared__ float red[8];
    int lane = threadIdx.x & 31, warp = threadIdx.x >> 5;
    if (lane == 0) red[warp] = s;
    __syncthreads();
    if (threadIdx.x == 0) {
        float t = 0.0f;
#pragma unroll
        for (int i = 0; i < 8; i++) t += red[i];
        g_Z[b*PACK + r] = t;
    }
}

// ---------------- Kernel C: bf16-split HMMA GEMM + symmetric epilogue ----------------
// per batch: C[1024(903),768] = Wp[.,1024] @ seq[1024,768] ; mirror to (t,s)
#define GBM 128
#define GBN 128
#define NST 3
#define TILEB 16384                // 128 rows x 128 B
#define STAGEB (4*TILEB)           // Ahi, Alo, Bhi, Blo
#define NKS 16                     // 1024 / 64

__global__ void __launch_bounds__(256, 1) mma_gemm(float* __restrict__ out) {
    extern __shared__ __align__(1024) char smc[];
    uint32_t sbase = smem_u32(smc);

    int tid = threadIdx.x, lane = tid & 31, wid = tid >> 5;
    int wm = wid & 1, wn = wid >> 1;          // 2 x 4 warp grid
    int b  = blockIdx.z;
    int m0 = blockIdx.y * GBM;
    int n0 = blockIdx.x * GBN;

    const char* gsrc[4] = {
        (const char*)(g_Whi  + ((size_t)b*PACK + m0)*LL),
        (const char*)(g_Wlo  + ((size_t)b*PACK + m0)*LL),
        (const char*)(g_BThi + ((size_t)b*DD   + n0)*LL),
        (const char*)(g_BTlo + ((size_t)b*DD   + n0)*LL)
    };

    auto load_stage = [&](int ks) {
        uint32_t sdst = sbase + (uint32_t)(ks % NST) * STAGEB;
        size_t kbyte = (size_t)ks * 128;       // 64 bf16
#pragma unroll
        for (int t4 = 0; t4 < 4; t4++) {
#pragma unroll
            for (int i = 0; i < 4; i++) {
                int idx = tid + i*256;         // 0..1023 chunks of 16B
                int row = idx >> 3, c = idx & 7;
                const char* src = gsrc[t4] + (size_t)row*2048 + kbyte + c*16;
                uint32_t so = (uint32_t)(row*128 + ((c ^ (row & 7)) << 4));
                cp16(sdst + t4*TILEB + so, src);
            }
        }
    };

    float acc[4][4][4];
#pragma unroll
    for (int i = 0; i < 4; i++)
#pragma unroll
        for (int j = 0; j < 4; j++)
#pragma unroll
            for (int k = 0; k < 4; k++) acc[i][j][k] = 0.0f;

    load_stage(0); CP_COMMIT();
    load_stage(1); CP_COMMIT();

    for (int ks = 0; ks < NKS; ks++) {
        if (ks < NKS - 2) CP_WAIT1(); else CP_WAIT0();
        __syncthreads();
        if (ks + 2 < NKS) { load_stage(ks + 2); CP_COMMIT(); }

        uint32_t s0 = sbase + (uint32_t)(ks % NST) * STAGEB;
#pragma unroll
        for (int kk = 0; kk < 4; kk++) {
            uint32_t ah[4][4], al[4][4];
#pragma unroll
            for (int mi = 0; mi < 4; mi++) {
                int row = wm*64 + mi*16 + (lane & 15);
                int c = kk*2 + (lane >> 4);
                uint32_t so = (uint32_t)(row*128 + ((c ^ (row & 7)) << 4));
                ldsm4(ah[mi][0], ah[mi][1], ah[mi][2], ah[mi][3], s0 + so);
                ldsm4(al[mi][0], al[mi][1], al[mi][2], al[mi][3], s0 + TILEB + so);
            }
            uint32_t bh[4][2], bl[4][2];
#pragma unroll
            for (int nj = 0; nj < 2; nj++) {
                int row = wn*32 + nj*16 + (lane & 15);
                int c = kk*2 + (lane >> 4);
                uint32_t so = (uint32_t)(row*128 + ((c ^ (row & 7)) << 4));
                uint32_t r0, r1, r2, r3;
                ldsm4(r0, r1, r2, r3, s0 + 2*TILEB + so);
                bh[2*nj][0] = r0; bh[2*nj][1] = r2;
                bh[2*nj+1][0] = r1; bh[2*nj+1][1] = r3;
                ldsm4(r0, r1, r2, r3, s0 + 3*TILEB + so);
                bl[2*nj][0] = r0; bl[2*nj][1] = r2;
                bl[2*nj+1][0] = r1; bl[2*nj+1][1] = r3;
            }
#pragma unroll
            for (int mi = 0; mi < 4; mi++)
#pragma unroll
                for (int ni = 0; ni < 4; ni++) {
                    mma16816(acc[mi][ni], ah[mi], bh[ni]);
                    mma16816(acc[mi][ni], ah[mi], bl[ni]);
                    mma16816(acc[mi][ni], al[mi], bh[ni]);
                }
        }
    }

    // epilogue: scale by 1/(Z+1e-5), mirror-write (s,t) and (t,s)
#pragma unroll
    for (int mi = 0; mi < 4; mi++) {
#pragma unroll
        for (int h = 0; h < 2; h++) {
            int r = m0 + wm*64 + mi*16 + h*8 + (lane >> 2);
            if (r < NPAIR) {
                int s = g_ps[r], t = g_pt[r];
                float scale = 1.0f / (g_Z[b*PACK + r] + 1e-5f);
                float* o1 = out + ((size_t)b*ST + s*NEE + t)*DD;
                float* o2 = out + ((size_t)b*ST + t*NEE + s)*DD;
#pragma unroll
                for (int ni = 0; ni < 4; ni++) {
                    int col = n0 + wn*32 + ni*8 + (lane & 3)*2;
                    float2 v;
                    v.x = acc[mi][ni][h*2+0] * scale;
                    v.y = acc[mi][ni][h*2+1] * scale;
                    *(float2*)(o1 + col) = v;
                    *(float2*)(o2 + col) = v;
                }
            }
        }
    }
}

// ---------------- launch ----------------
extern "C" void kernel_launch(void* const* d_in, const int* in_sizes, int n_in,
                              void* d_out, int out_size) {
    const float* seq   = (const float*)d_in[0];   // [4,1024,768]
    const float* att   = (const float*)d_in[1];   // [4,12,1024,1024]
    const int*   midx  = (const int*)  d_in[2];   // [4,42,8]
    const int*   mmask = (const int*)  d_in[3];   // [4,42,8]
    float*       out   = (float*)d_out;           // [4,42,42,768]

    cudaFuncSetAttribute(mma_gemm, cudaFuncAttributeMaxDynamicSharedMemorySize, NST*STAGEB);

    init_pairs<<<7, 256>>>();
    transpose_conv<<<dim3(LL/32, DD/32, BB), 256>>>(seq);
    ent_att_kernel<<<BB*HH*NEE, 256>>>(att, midx, mmask);
    htatt_kernel<<<dim3(LL/TL, BB), 256>>>();
    rowsum_kernel<<<BB*NPAIR, 256>>>();
    mma_gemm<<<dim3(DD/GBN, PACK/GBM, BB), 256, NST*STAGEB>>>(out);
}

// round 5
// speedup vs baseline: 2.4389x; 1.0719x over previous
#include <cuda_runtime.h>
#include <cuda_bf16.h>
#include <cstdint>

// ---------------- problem constants ----------------
#define BB 4
#define LL 1024
#define DD 768
#define HH 12
#define NEE 42
#define MM 8
#define ST (NEE*NEE)     // 1764
#define NPAIR 903        // pairs with s<=t
#define PACK 1024        // padded packed rows (8 x 128)

// ---------------- device scratch ----------------
__device__ __nv_bfloat16 g_Whi[(size_t)BB*PACK*LL];   // packed symmetric W hi
__device__ __nv_bfloat16 g_Wlo[(size_t)BB*PACK*LL];   // packed symmetric W lo
__device__ __nv_bfloat16 g_BThi[(size_t)BB*DD*LL];    // seq^T hi [b][d][l]
__device__ __nv_bfloat16 g_BTlo[(size_t)BB*DD*LL];
__device__ float         g_Z[BB*PACK];                // packed row sums (atomic)
__device__ int           g_ps[PACK];                  // packed row -> s
__device__ int           g_pt[PACK];                  // packed row -> t

// ---------------- PTX helpers ----------------
__device__ __forceinline__ uint32_t smem_u32(const void* p) {
    uint32_t a;
    asm("{ .reg .u64 t; cvta.to.shared.u64 t, %1; cvt.u32.u64 %0, t; }" : "=r"(a) : "l"(p));
    return a;
}
__device__ __forceinline__ void cp16(uint32_t dst, const void* src) {
    asm volatile("cp.async.cg.shared.global [%0], [%1], 16;" :: "r"(dst), "l"(src));
}
#define CP_COMMIT() asm volatile("cp.async.commit_group;" ::: "memory")
#define CP_WAIT1()  asm volatile("cp.async.wait_group 1;" ::: "memory")
#define CP_WAIT0()  asm volatile("cp.async.wait_group 0;" ::: "memory")

__device__ __forceinline__ void ldsm4(uint32_t& r0, uint32_t& r1, uint32_t& r2, uint32_t& r3,
                                      uint32_t addr) {
    asm volatile("ldmatrix.sync.aligned.m8n8.x4.shared.b16 {%0,%1,%2,%3}, [%4];"
                 : "=r"(r0), "=r"(r1), "=r"(r2), "=r"(r3) : "r"(addr));
}
__device__ __forceinline__ void mma16816(float* d, const uint32_t* a, const uint32_t* b) {
    asm volatile(
        "mma.sync.aligned.m16n8k16.row.col.f32.bf16.bf16.f32 "
        "{%0,%1,%2,%3},{%4,%5,%6,%7},{%8,%9},{%0,%1,%2,%3};"
        : "+f"(d[0]), "+f"(d[1]), "+f"(d[2]), "+f"(d[3])
        : "r"(a[0]), "r"(a[1]), "r"(a[2]), "r"(a[3]), "r"(b[0]), "r"(b[1]));
}

// ---------------- Kernel P: pair tables + Z zero ----------------
__global__ void init_pairs() {
    int i = blockIdx.x * blockDim.x + threadIdx.x;
    if (i < BB*PACK) g_Z[i] = 0.0f;
    if (i < ST) {
        int s = i / NEE, t = i % NEE;
        if (s <= t) {
            int r = s*NEE - s*(s+1)/2 + t;
            g_ps[r] = s; g_pt[r] = t;
        }
    }
}

// ---------------- Kernel T: transpose+split seq -> BT hi/lo ----------------
__global__ void __launch_bounds__(256) transpose_conv(const float* __restrict__ seq) {
    __shared__ float t[32][33];
    int b = blockIdx.z;
    int l0 = blockIdx.x * 32, d0 = blockIdx.y * 32;
    int tx = threadIdx.x & 31, ty = threadIdx.x >> 5;
#pragma unroll
    for (int j = ty; j < 32; j += 8)
        t[j][tx] = seq[((size_t)b*LL + l0 + j)*DD + d0 + tx];
    __syncthreads();
#pragma unroll
    for (int j = ty; j < 32; j += 8) {
        float v = t[tx][j];
        __nv_bfloat16 hi = __float2bfloat16(v);
        float lo = v - __bfloat162float(hi);
        size_t o = ((size_t)b*DD + d0 + j)*LL + l0 + tx;
        g_BThi[o] = hi;
        g_BTlo[o] = __float2bfloat16(lo);
    }
}

// ---------------- Kernel F: fused ent_att + Gram + split + Z ----------------
// grid (LL/32, BB), 512 threads; dyn smem = 12*42*32 floats = 64512 B
__global__ void __launch_bounds__(512) fuse_kernel(const float* __restrict__ att,
                                                   const int* __restrict__ midx,
                                                   const int* __restrict__ mmask) {
    extern __shared__ float As[];           // [h*NEE+e][32]
    __shared__ int   sidx[NEE*MM];
    __shared__ int   scnt[NEE];
    __shared__ float sinv[NEE];

    int tid = threadIdx.x;
    int b = blockIdx.y, l0 = blockIdx.x * 32;

    if (tid < NEE) {
        int e = tid, k = 0;
        const int* ip = midx  + (b*NEE + e)*MM;
        const int* mp = mmask + (b*NEE + e)*MM;
#pragma unroll
        for (int m = 0; m < MM; m++) {
            int i = ip[m] + 1;
            if (mp[m] > 0 && i < LL) sidx[e*MM + (k++)] = i;
        }
        scnt[e] = k;
        sinv[e] = 1.0f / (float)(k > 0 ? k : 1);
    }
    __syncthreads();

    int lane = tid & 31, warp = tid >> 5;

    // gather: one warp per (h,e); lanes cover 32 l values (coalesced 128B)
    const float* ab0 = att + (size_t)b * HH * LL * LL + l0 + lane;
    for (int he = warp; he < HH*NEE; he += 16) {
        int h = he / NEE, e = he % NEE;
        const float* ab = ab0 + (size_t)h * LL * LL;
        int c = scnt[e];
        float s = 0.0f;
        for (int m = 0; m < c; m++)
            s += ab[(size_t)sidx[e*MM + m] * LL];
        As[he*32 + lane] = s * sinv[e];
    }
    __syncthreads();

    // Gram: lane = l, warp = t-stride group
    const float invH = 1.0f / (float)HH;
    for (int s = 0; s < NEE; s++) {
        float as[HH];
#pragma unroll
        for (int h = 0; h < HH; h++)
            as[h] = As[(h*NEE + s)*32 + lane];
        int rbase = s*NEE - s*(s+1)/2;
        for (int t = s + warp; t < NEE; t += 16) {
            float acc = 0.0f;
#pragma unroll
            for (int h = 0; h < HH; h++)
                acc = fmaf(as[h], As[(h*NEE + t)*32 + lane], acc);
            float w = acc * invH;
            __nv_bfloat16 hi = __float2bfloat16(w);
            float lo = w - __bfloat162float(hi);
            size_t o = ((size_t)b*PACK + rbase + t)*LL + l0 + lane;
            g_Whi[o] = hi;
            g_Wlo[o] = __float2bfloat16(lo);
            // Z partial: reduce 32 l's, atomic accumulate
            float zs = w;
#pragma unroll
            for (int off = 16; off > 0; off >>= 1)
                zs += __shfl_xor_sync(0xffffffffu, zs, off);
            if (lane == 0) atomicAdd(&g_Z[b*PACK + rbase + t], zs);
        }
    }
}

// ---------------- Kernel C: bf16-split HMMA GEMM + symmetric epilogue ----------------
// per batch: C[1024(903),768] = Wp[.,1024] @ seq[1024,768]; tiles 128x96, mirror writes
#define GBM 128
#define GBN 96
#define NST 3
#define OFF_AHI 0
#define OFF_ALO 16384
#define OFF_BHI 32768
#define OFF_BLO 45056
#define STAGEB  57344
#define NKS 16                     // 1024 / 64

__global__ void __launch_bounds__(256, 1) mma_gemm(float* __restrict__ out) {
    extern __shared__ __align__(1024) char smc[];
    uint32_t sbase = smem_u32(smc);

    int tid = threadIdx.x, lane = tid & 31, wid = tid >> 5;
    int wm = wid & 3, wn = wid >> 2;          // 4 x 2 warp grid (warp tile 32x48)
    int b  = blockIdx.z;
    int m0 = blockIdx.y * GBM;
    int n0 = blockIdx.x * GBN;

    const char* gA[2] = {
        (const char*)(g_Whi  + ((size_t)b*PACK + m0)*LL),
        (const char*)(g_Wlo  + ((size_t)b*PACK + m0)*LL)
    };
    const char* gB[2] = {
        (const char*)(g_BThi + ((size_t)b*DD   + n0)*LL),
        (const char*)(g_BTlo + ((size_t)b*DD   + n0)*LL)
    };

    auto load_stage = [&](int ks) {
        uint32_t sdst = sbase + (uint32_t)(ks % NST) * STAGEB;
        size_t kbyte = (size_t)ks * 128;       // 64 bf16
#pragma unroll
        for (int t4 = 0; t4 < 2; t4++) {       // A tiles: 128 rows
#pragma unroll
            for (int i = 0; i < 4; i++) {
                int idx = tid + i*256;         // 0..1023
                int row = idx >> 3, c = idx & 7;
                const char* src = gA[t4] + (size_t)row*2048 + kbyte + c*16;
                uint32_t so = (uint32_t)(row*128 + ((c ^ (row & 7)) << 4));
                cp16(sdst + OFF_AHI + t4*16384 + so, src);
            }
        }
#pragma unroll
        for (int t4 = 0; t4 < 2; t4++) {       // B tiles: 96 rows
#pragma unroll
            for (int i = 0; i < 3; i++) {
                int idx = tid + i*256;         // 0..767
                int row = idx >> 3, c = idx & 7;
                const char* src = gB[t4] + (size_t)row*2048 + kbyte + c*16;
                uint32_t so = (uint32_t)(row*128 + ((c ^ (row & 7)) << 4));
                cp16(sdst + OFF_BHI + t4*12288 + so, src);
            }
        }
    };

    float acc[2][6][4];
#pragma unroll
    for (int i = 0; i < 2; i++)
#pragma unroll
        for (int j = 0; j < 6; j++)
#pragma unroll
            for (int k = 0; k < 4; k++) acc[i][j][k] = 0.0f;

    load_stage(0); CP_COMMIT();
    load_stage(1); CP_COMMIT();

    for (int ks = 0; ks < NKS; ks++) {
        if (ks < NKS - 2) CP_WAIT1(); else CP_WAIT0();
        __syncthreads();
        if (ks + 2 < NKS) { load_stage(ks + 2); CP_COMMIT(); }

        uint32_t s0 = sbase + (uint32_t)(ks % NST) * STAGEB;
#pragma unroll
        for (int kk = 0; kk < 4; kk++) {
            uint32_t ah[2][4], al[2][4];
#pragma unroll
            for (int mi = 0; mi < 2; mi++) {
                int row = wm*32 + mi*16 + (lane & 15);
                int c = kk*2 + (lane >> 4);
                uint32_t so = (uint32_t)(row*128 + ((c ^ (row & 7)) << 4));
                ldsm4(ah[mi][0], ah[mi][1], ah[mi][2], ah[mi][3], s0 + OFF_AHI + so);
                ldsm4(al[mi][0], al[mi][1], al[mi][2], al[mi][3], s0 + OFF_ALO + so);
            }
            uint32_t bh[6][2], bl[6][2];
#pragma unroll
            for (int nj = 0; nj < 3; nj++) {
                int row = wn*48 + nj*16 + (lane & 15);
                int c = kk*2 + (lane >> 4);
                uint32_t so = (uint32_t)(row*128 + ((c ^ (row & 7)) << 4));
                uint32_t r0, r1, r2, r3;
                ldsm4(r0, r1, r2, r3, s0 + OFF_BHI + so);
                bh[2*nj][0] = r0; bh[2*nj][1] = r2;
                bh[2*nj+1][0] = r1; bh[2*nj+1][1] = r3;
                ldsm4(r0, r1, r2, r3, s0 + OFF_BLO + so);
                bl[2*nj][0] = r0; bl[2*nj][1] = r2;
                bl[2*nj+1][0] = r1; bl[2*nj+1][1] = r3;
            }
#pragma unroll
            for (int mi = 0; mi < 2; mi++)
#pragma unroll
                for (int ni = 0; ni < 6; ni++) {
                    mma16816(acc[mi][ni], ah[mi], bh[ni]);
                    mma16816(acc[mi][ni], ah[mi], bl[ni]);
                    mma16816(acc[mi][ni], al[mi], bh[ni]);
                }
        }
    }

    // epilogue: scale by 1/(Z+1e-5), mirror-write (s,t) and (t,s)
#pragma unroll
    for (int mi = 0; mi < 2; mi++) {
#pragma unroll
        for (int h = 0; h < 2; h++) {
            int r = m0 + wm*32 + mi*16 + h*8 + (lane >> 2);
            if (r < NPAIR) {
                int s = g_ps[r], t = g_pt[r];
                float scale = 1.0f / (g_Z[b*PACK + r] + 1e-5f);
                float* o1 = out + ((size_t)b*ST + s*NEE + t)*DD;
                float* o2 = out + ((size_t)b*ST + t*NEE + s)*DD;
#pragma unroll
                for (int ni = 0; ni < 6; ni++) {
                    int col = n0 + wn*48 + ni*8 + (lane & 3)*2;
                    float2 v;
                    v.x = acc[mi][ni][h*2+0] * scale;
                    v.y = acc[mi][ni][h*2+1] * scale;
                    *(float2*)(o1 + col) = v;
                    *(float2*)(o2 + col) = v;
                }
            }
        }
    }
}

// ---------------- launch ----------------
extern "C" void kernel_launch(void* const* d_in, const int* in_sizes, int n_in,
                              void* d_out, int out_size) {
    const float* seq   = (const float*)d_in[0];   // [4,1024,768]
    const float* att   = (const float*)d_in[1];   // [4,12,1024,1024]
    const int*   midx  = (const int*)  d_in[2];   // [4,42,8]
    const int*   mmask = (const int*)  d_in[3];   // [4,42,8]
    float*       out   = (float*)d_out;           // [4,42,42,768]

    cudaFuncSetAttribute(fuse_kernel, cudaFuncAttributeMaxDynamicSharedMemorySize, 64512);
    cudaFuncSetAttribute(mma_gemm, cudaFuncAttributeMaxDynamicSharedMemorySize, NST*STAGEB);

    init_pairs<<<16, 256>>>();
    transpose_conv<<<dim3(LL/32, DD/32, BB), 256>>>(seq);
    fuse_kernel<<<dim3(LL/32, BB), 512, 64512>>>(att, midx, mmask);
    mma_gemm<<<dim3(DD/GBN, PACK/GBM, BB), 256, NST*STAGEB>>>(out);
}

// round 6
// speedup vs baseline: 3.7143x; 1.5230x over previous
#include <cuda_runtime.h>
#include <cuda_fp16.h>
#include <cstdint>

// ---------------- problem constants ----------------
#define BB 4
#define LL 1024
#define DD 768
#define HH 12
#define NEE 42
#define MM 8
#define ST (NEE*NEE)     // 1764
#define NPAIR 903        // pairs with s<=t
#define PACK 1024        // padded packed rows (8 x 128)

// ---------------- device scratch ----------------
__device__ __half g_Wh[(size_t)BB*PACK*LL];   // packed symmetric W (fp16)
__device__ __half g_BT[(size_t)BB*DD*LL];     // seq^T (fp16) [b][d][l]
__device__ float  g_Z[BB*PACK];               // packed row sums (atomic)
__device__ int    g_ps[PACK];                 // packed row -> s
__device__ int    g_pt[PACK];                 // packed row -> t

// ---------------- PTX helpers ----------------
__device__ __forceinline__ uint32_t smem_u32(const void* p) {
    uint32_t a;
    asm("{ .reg .u64 t; cvta.to.shared.u64 t, %1; cvt.u32.u64 %0, t; }" : "=r"(a) : "l"(p));
    return a;
}
__device__ __forceinline__ void cp16(uint32_t dst, const void* src) {
    asm volatile("cp.async.cg.shared.global [%0], [%1], 16;" :: "r"(dst), "l"(src));
}
#define CP_COMMIT() asm volatile("cp.async.commit_group;" ::: "memory")
#define CP_WAIT2()  asm volatile("cp.async.wait_group 2;" ::: "memory")
#define CP_WAIT0()  asm volatile("cp.async.wait_group 0;" ::: "memory")

__device__ __forceinline__ void ldsm4(uint32_t& r0, uint32_t& r1, uint32_t& r2, uint32_t& r3,
                                      uint32_t addr) {
    asm volatile("ldmatrix.sync.aligned.m8n8.x4.shared.b16 {%0,%1,%2,%3}, [%4];"
                 : "=r"(r0), "=r"(r1), "=r"(r2), "=r"(r3) : "r"(addr));
}
__device__ __forceinline__ void mma16816(float* d, const uint32_t* a, const uint32_t* b) {
    asm volatile(
        "mma.sync.aligned.m16n8k16.row.col.f32.f16.f16.f32 "
        "{%0,%1,%2,%3},{%4,%5,%6,%7},{%8,%9},{%0,%1,%2,%3};"
        : "+f"(d[0]), "+f"(d[1]), "+f"(d[2]), "+f"(d[3])
        : "r"(a[0]), "r"(a[1]), "r"(a[2]), "r"(a[3]), "r"(b[0]), "r"(b[1]));
}

// ---------------- Kernel T: transpose+convert seq -> BT fp16; also init Z + pair tables ----------------
__global__ void __launch_bounds__(256) transpose_conv(const float* __restrict__ seq) {
    __shared__ float t[32][33];
    int b = blockIdx.z;
    int l0 = blockIdx.x * 32, d0 = blockIdx.y * 32;

    // fold init work into the first column of blocks
    if (blockIdx.x == 0 && blockIdx.y == 0) {
#pragma unroll
        for (int i = threadIdx.x; i < PACK; i += 256) g_Z[b*PACK + i] = 0.0f;
        if (b == 0) {
            for (int i = threadIdx.x; i < ST; i += 256) {
                int s = i / NEE, tt = i % NEE;
                if (s <= tt) {
                    int r = s*NEE - s*(s+1)/2 + tt;
                    g_ps[r] = s; g_pt[r] = tt;
                }
            }
        }
    }

    int tx = threadIdx.x & 31, ty = threadIdx.x >> 5;
#pragma unroll
    for (int j = ty; j < 32; j += 8)
        t[j][tx] = seq[((size_t)b*LL + l0 + j)*DD + d0 + tx];
    __syncthreads();
#pragma unroll
    for (int j = ty; j < 32; j += 8) {
        size_t o = ((size_t)b*DD + d0 + j)*LL + l0 + tx;
        g_BT[o] = __float2half(t[tx][j]);
    }
}

// ---------------- Kernel F: fused ent_att + Gram + fp16 convert + Z ----------------
// grid (LL/32, BB), 512 threads; dyn smem = 12*42*32 floats = 64512 B
__global__ void __launch_bounds__(512) fuse_kernel(const float* __restrict__ att,
                                                   const int* __restrict__ midx,
                                                   const int* __restrict__ mmask) {
    extern __shared__ float As[];           // [h*NEE+e][32]
    __shared__ int   sidx[NEE*MM];
    __shared__ int   scnt[NEE];
    __shared__ float sinv[NEE];

    int tid = threadIdx.x;
    int b = blockIdx.y, l0 = blockIdx.x * 32;

    if (tid < NEE) {
        int e = tid, k = 0;
        const int* ip = midx  + (b*NEE + e)*MM;
        const int* mp = mmask + (b*NEE + e)*MM;
#pragma unroll
        for (int m = 0; m < MM; m++) {
            int i = ip[m] + 1;
            if (mp[m] > 0 && i < LL) sidx[e*MM + (k++)] = i;
        }
        scnt[e] = k;
        sinv[e] = 1.0f / (float)(k > 0 ? k : 1);
    }
    __syncthreads();

    int lane = tid & 31, warp = tid >> 5;

    // gather: one warp per (h,e); lanes cover 32 l values (coalesced 128B)
    const float* ab0 = att + (size_t)b * HH * LL * LL + l0 + lane;
    for (int he = warp; he < HH*NEE; he += 16) {
        int h = he / NEE, e = he % NEE;
        const float* ab = ab0 + (size_t)h * LL * LL;
        int c = scnt[e];
        float s = 0.0f;
        for (int m = 0; m < c; m++)
            s += ab[(size_t)sidx[e*MM + m] * LL];
        As[he*32 + lane] = s * sinv[e];
    }
    __syncthreads();

    // Gram: lane = l, warp = t-stride group
    const float invH = 1.0f / (float)HH;
    for (int s = 0; s < NEE; s++) {
        float as[HH];
#pragma unroll
        for (int h = 0; h < HH; h++)
            as[h] = As[(h*NEE + s)*32 + lane];
        int rbase = s*NEE - s*(s+1)/2;
        for (int t = s + warp; t < NEE; t += 16) {
            float acc = 0.0f;
#pragma unroll
            for (int h = 0; h < HH; h++)
                acc = fmaf(as[h], As[(h*NEE + t)*32 + lane], acc);
            float w = acc * invH;
            g_Wh[((size_t)b*PACK + rbase + t)*LL + l0 + lane] = __float2half(w);
            // Z partial: reduce 32 l's, atomic accumulate (fp32 exact-path)
            float zs = w;
#pragma unroll
            for (int off = 16; off > 0; off >>= 1)
                zs += __shfl_xor_sync(0xffffffffu, zs, off);
            if (lane == 0) atomicAdd(&g_Z[b*PACK + rbase + t], zs);
        }
    }
}

// ---------------- Kernel C: fp16 HMMA GEMM + symmetric epilogue ----------------
// per batch: C[1024(903),768] = Wp[.,1024] @ seq[1024,768]; tiles 128x96, mirror writes
#define GBM 128
#define GBN 96
#define NST 4
#define OFF_A 0
#define OFF_B 16384
#define STAGEB 28672               // A 16KB + B 12KB
#define NKS 16                     // 1024 / 64

__global__ void __launch_bounds__(256, 2) mma_gemm(float* __restrict__ out) {
    extern __shared__ __align__(1024) char smc[];
    uint32_t sbase = smem_u32(smc);

    int tid = threadIdx.x, lane = tid & 31, wid = tid >> 5;
    int wm = wid & 3, wn = wid >> 2;          // 4 x 2 warp grid (warp tile 32x48)
    int b  = blockIdx.z;
    int m0 = blockIdx.y * GBM;
    int n0 = blockIdx.x * GBN;

    const char* gA = (const char*)(g_Wh + ((size_t)b*PACK + m0)*LL);
    const char* gB = (const char*)(g_BT + ((size_t)b*DD   + n0)*LL);

    auto load_stage = [&](int ks) {
        uint32_t sdst = sbase + (uint32_t)(ks % NST) * STAGEB;
        size_t kbyte = (size_t)ks * 128;       // 64 fp16
#pragma unroll
        for (int i = 0; i < 4; i++) {          // A: 128 rows x 8 chunks
            int idx = tid + i*256;             // 0..1023
            int row = idx >> 3, c = idx & 7;
            const char* src = gA + (size_t)row*2048 + kbyte + c*16;
            uint32_t so = (uint32_t)(row*128 + ((c ^ (row & 7)) << 4));
            cp16(sdst + OFF_A + so, src);
        }
#pragma unroll
        for (int i = 0; i < 3; i++) {          // B: 96 rows x 8 chunks
            int idx = tid + i*256;             // 0..767
            int row = idx >> 3, c = idx & 7;
            const char* src = gB + (size_t)row*2048 + kbyte + c*16;
            uint32_t so = (uint32_t)(row*128 + ((c ^ (row & 7)) << 4));
            cp16(sdst + OFF_B + so, src);
        }
    };

    float acc[2][6][4];
#pragma unroll
    for (int i = 0; i < 2; i++)
#pragma unroll
        for (int j = 0; j < 6; j++)
#pragma unroll
            for (int k = 0; k < 4; k++) acc[i][j][k] = 0.0f;

    load_stage(0); CP_COMMIT();
    load_stage(1); CP_COMMIT();
    load_stage(2); CP_COMMIT();

    for (int ks = 0; ks < NKS; ks++) {
        if (ks < NKS - 3) CP_WAIT2(); else CP_WAIT0();
        __syncthreads();
        if (ks + 3 < NKS) { load_stage(ks + 3); CP_COMMIT(); }

        uint32_t s0 = sbase + (uint32_t)(ks % NST) * STAGEB;
#pragma unroll
        for (int kk = 0; kk < 4; kk++) {
            uint32_t ah[2][4];
#pragma unroll
            for (int mi = 0; mi < 2; mi++) {
                int row = wm*32 + mi*16 + (lane & 15);
                int c = kk*2 + (lane >> 4);
                uint32_t so = (uint32_t)(row*128 + ((c ^ (row & 7)) << 4));
                ldsm4(ah[mi][0], ah[mi][1], ah[mi][2], ah[mi][3], s0 + OFF_A + so);
            }
            uint32_t bh[6][2];
#pragma unroll
            for (int nj = 0; nj < 3; nj++) {
                int row = wn*48 + nj*16 + (lane & 15);
                int c = kk*2 + (lane >> 4);
                uint32_t so = (uint32_t)(row*128 + ((c ^ (row & 7)) << 4));
                uint32_t r0, r1, r2, r3;
                ldsm4(r0, r1, r2, r3, s0 + OFF_B + so);
                bh[2*nj][0] = r0; bh[2*nj][1] = r2;
                bh[2*nj+1][0] = r1; bh[2*nj+1][1] = r3;
            }
#pragma unroll
            for (int mi = 0; mi < 2; mi++)
#pragma unroll
                for (int ni = 0; ni < 6; ni++)
                    mma16816(acc[mi][ni], ah[mi], bh[ni]);
        }
    }

    // epilogue: scale by 1/(Z+1e-5), mirror-write (s,t) and (t,s)
#pragma unroll
    for (int mi = 0; mi < 2; mi++) {
#pragma unroll
        for (int h = 0; h < 2; h++) {
            int r = m0 + wm*32 + mi*16 + h*8 + (lane >> 2);
            if (r < NPAIR) {
                int s = g_ps[r], t = g_pt[r];
                float scale = 1.0f / (g_Z[b*PACK + r] + 1e-5f);
                float* o1 = out + ((size_t)b*ST + s*NEE + t)*DD;
                float* o2 = out + ((size_t)b*ST + t*NEE + s)*DD;
#pragma unroll
                for (int ni = 0; ni < 6; ni++) {
                    int col = n0 + wn*48 + ni*8 + (lane & 3)*2;
                    float2 v;
                    v.x = acc[mi][ni][h*2+0] * scale;
                    v.y = acc[mi][ni][h*2+1] * scale;
                    *(float2*)(o1 + col) = v;
                    *(float2*)(o2 + col) = v;
                }
            }
        }
    }
}

// ---------------- launch ----------------
extern "C" void kernel_launch(void* const* d_in, const int* in_sizes, int n_in,
                              void* d_out, int out_size) {
    const float* seq   = (const float*)d_in[0];   // [4,1024,768]
    const float* att   = (const float*)d_in[1];   // [4,12,1024,1024]
    const int*   midx  = (const int*)  d_in[2];   // [4,42,8]
    const int*   mmask = (const int*)  d_in[3];   // [4,42,8]
    float*       out   = (float*)d_out;           // [4,42,42,768]

    cudaFuncSetAttribute(fuse_kernel, cudaFuncAttributeMaxDynamicSharedMemorySize, 64512);
    cudaFuncSetAttribute(mma_gemm, cudaFuncAttributeMaxDynamicSharedMemorySize, NST*STAGEB);

    transpose_conv<<<dim3(LL/32, DD/32, BB), 256>>>(seq);
    fuse_kernel<<<dim3(LL/32, BB), 512, 64512>>>(att, midx, mmask);
    mma_gemm<<<dim3(DD/GBN, PACK/GBM, BB), 256, NST*STAGEB>>>(out);
}

// round 7
// speedup vs baseline: 5.0964x; 1.3721x over previous
#include <cuda_runtime.h>
#include <cuda_fp16.h>
#include <cstdint>

// ---------------- problem constants ----------------
#define BB 4
#define LL 1024
#define DD 768
#define HH 12
#define NEE 42
#define MM 8
#define ST (NEE*NEE)     // 1764
#define NPAIR 903        // pairs with s<=t
#define PACK 1024        // padded packed rows (8 x 128)

// ---------------- device scratch ----------------
__device__ __half g_Wh[(size_t)BB*PACK*LL];   // packed symmetric W (fp16)
__device__ __half g_BT[(size_t)BB*DD*LL];     // seq^T (fp16) [b][d][l]
__device__ float  g_Z[BB*PACK];               // packed row sums (atomic)
__device__ int    g_ps[PACK];                 // packed row -> s
__device__ int    g_pt[PACK];                 // packed row -> t

// ---------------- PTX helpers ----------------
__device__ __forceinline__ uint32_t smem_u32(const void* p) {
    uint32_t a;
    asm("{ .reg .u64 t; cvta.to.shared.u64 t, %1; cvt.u32.u64 %0, t; }" : "=r"(a) : "l"(p));
    return a;
}
__device__ __forceinline__ void cp16(uint32_t dst, const void* src) {
    asm volatile("cp.async.cg.shared.global [%0], [%1], 16;" :: "r"(dst), "l"(src));
}
#define CP_COMMIT() asm volatile("cp.async.commit_group;" ::: "memory")
#define CP_WAIT2()  asm volatile("cp.async.wait_group 2;" ::: "memory")
#define CP_WAIT0()  asm volatile("cp.async.wait_group 0;" ::: "memory")

__device__ __forceinline__ void ldsm4(uint32_t& r0, uint32_t& r1, uint32_t& r2, uint32_t& r3,
                                      uint32_t addr) {
    asm volatile("ldmatrix.sync.aligned.m8n8.x4.shared.b16 {%0,%1,%2,%3}, [%4];"
                 : "=r"(r0), "=r"(r1), "=r"(r2), "=r"(r3) : "r"(addr));
}
__device__ __forceinline__ void mma16816(float* d, const uint32_t* a, const uint32_t* b) {
    asm volatile(
        "mma.sync.aligned.m16n8k16.row.col.f32.f16.f16.f32 "
        "{%0,%1,%2,%3},{%4,%5,%6,%7},{%8,%9},{%0,%1,%2,%3};"
        : "+f"(d[0]), "+f"(d[1]), "+f"(d[2]), "+f"(d[3])
        : "r"(a[0]), "r"(a[1]), "r"(a[2]), "r"(a[3]), "r"(b[0]), "r"(b[1]));
}

// ---------------- Kernel T: transpose+convert seq -> BT fp16; init Z + pair tables ----------------
// 64 l x 32 d tiles, 256 threads; half2 stores (128B/warp)
__global__ void __launch_bounds__(256) transpose_conv(const float* __restrict__ seq) {
    __shared__ float t[64][33];
    int b = blockIdx.z;
    int l0 = blockIdx.x * 64, d0 = blockIdx.y * 32;
    int lane = threadIdx.x & 31, w = threadIdx.x >> 5;

    if (blockIdx.x == 0 && blockIdx.y == 0) {
        for (int i = threadIdx.x; i < PACK; i += 256) g_Z[b*PACK + i] = 0.0f;
        if (b == 0) {
            for (int i = threadIdx.x; i < ST; i += 256) {
                int s = i / NEE, tt = i % NEE;
                if (s <= tt) {
                    int r = s*NEE - s*(s+1)/2 + tt;
                    g_ps[r] = s; g_pt[r] = tt;
                }
            }
        }
    }

#pragma unroll
    for (int jj = 0; jj < 8; jj++) {
        int l = w + jj*8;                  // 0..63
        t[l][lane] = seq[((size_t)b*LL + l0 + l)*DD + d0 + lane];
    }
    __syncthreads();
#pragma unroll
    for (int jj = 0; jj < 4; jj++) {
        int d = w + jj*8;                  // 0..31
        __half2 v = __floats2half2_rn(t[2*lane][d], t[2*lane + 1][d]);
        *(__half2*)(&g_BT[((size_t)b*DD + d0 + d)*LL + l0 + 2*lane]) = v;
    }
}

// ---------------- Kernel F: fused ent_att + Gram + fp16 convert + Z ----------------
// grid (LL/32, BB), 1024 threads; dyn smem = 12*42*32 floats = 64512 B
__global__ void __launch_bounds__(1024) fuse_kernel(const float* __restrict__ att,
                                                    const int* __restrict__ midx,
                                                    const int* __restrict__ mmask) {
    extern __shared__ float As[];           // [h*NEE+e][32]
    __shared__ int   sidx[NEE*MM];
    __shared__ int   scnt[NEE];
    __shared__ float sinv[NEE];

    int tid = threadIdx.x;
    int b = blockIdx.y, l0 = blockIdx.x * 32;

    if (tid < NEE) {
        int e = tid, k = 0;
        const int* ip = midx  + (b*NEE + e)*MM;
        const int* mp = mmask + (b*NEE + e)*MM;
#pragma unroll
        for (int m = 0; m < MM; m++) {
            int i = ip[m] + 1;
            if (mp[m] > 0 && i < LL) sidx[e*MM + (k++)] = i;
        }
        scnt[e] = k;
        sinv[e] = 1.0f / (float)(k > 0 ? k : 1);
        for (int m = k; m < MM; m++) sidx[e*MM + m] = 0;   // pad -> L2-hot row 0
    }
    __syncthreads();

    int lane = tid & 31, warp = tid >> 5;   // 32 warps

    // gather: one warp per (h,e); fixed-8 unrolled predicated loads (MLP=8)
    const float* ab0 = att + (size_t)b * HH * LL * LL + l0 + lane;
    for (int he = warp; he < HH*NEE; he += 32) {
        int h = he / NEE, e = he % NEE;
        const float* ab = ab0 + (size_t)h * LL * LL;
        int c = scnt[e];
        float s = 0.0f;
#pragma unroll
        for (int m = 0; m < MM; m++) {
            float v = ab[(size_t)sidx[e*MM + m] * LL];
            s += (m < c) ? v : 0.0f;
        }
        As[he*32 + lane] = s * sinv[e];
    }
    __syncthreads();

    // Gram: lane = l, warp = t-stride group (stride 32)
    const float invH = 1.0f / (float)HH;
    for (int s = 0; s < NEE; s++) {
        if (s + warp < NEE) {
            float as[HH];
#pragma unroll
            for (int h = 0; h < HH; h++)
                as[h] = As[(h*NEE + s)*32 + lane];
            int rbase = s*NEE - s*(s+1)/2;
            int t = s + warp;               // at most one t per warp per s (stride 32 > 42-s)
            {
                float acc = 0.0f;
#pragma unroll
                for (int h = 0; h < HH; h++)
                    acc = fmaf(as[h], As[(h*NEE + t)*32 + lane], acc);
                float w = acc * invH;
                g_Wh[((size_t)b*PACK + rbase + t)*LL + l0 + lane] = __float2half(w);
                float zs = w;
#pragma unroll
                for (int off = 16; off > 0; off >>= 1)
                    zs += __shfl_xor_sync(0xffffffffu, zs, off);
                if (lane == 0) atomicAdd(&g_Z[b*PACK + rbase + t], zs);
            }
        }
        // warps with s+warp+32 < NEE handle second t (only when 42-s > 32, i.e. s < 10)
        int t2 = s + warp + 32;
        if (t2 < NEE) {
            float as[HH];
#pragma unroll
            for (int h = 0; h < HH; h++)
                as[h] = As[(h*NEE + s)*32 + lane];
            int rbase = s*NEE - s*(s+1)/2;
            float acc = 0.0f;
#pragma unroll
            for (int h = 0; h < HH; h++)
                acc = fmaf(as[h], As[(h*NEE + t2)*32 + lane], acc);
            float w = acc * invH;
            g_Wh[((size_t)b*PACK + rbase + t2)*LL + l0 + lane] = __float2half(w);
            float zs = w;
#pragma unroll
            for (int off = 16; off > 0; off >>= 1)
                zs += __shfl_xor_sync(0xffffffffu, zs, off);
            if (lane == 0) atomicAdd(&g_Z[b*PACK + rbase + t2], zs);
        }
    }
}

// ---------------- Kernel C: fp16 HMMA GEMM + symmetric epilogue ----------------
// per batch: C[1024(903),768] = Wp[.,1024] @ seq[1024,768]; tiles 128x96, mirror writes
#define GBM 128
#define GBN 96
#define NST 4
#define OFF_A 0
#define OFF_B 16384
#define STAGEB 28672               // A 16KB + B 12KB
#define NKS 16                     // 1024 / 64

__global__ void __launch_bounds__(256, 2) mma_gemm(float* __restrict__ out) {
    extern __shared__ __align__(1024) char smc[];
    uint32_t sbase = smem_u32(smc);

    int tid = threadIdx.x, lane = tid & 31, wid = tid >> 5;
    int wm = wid & 3, wn = wid >> 2;          // 4 x 2 warp grid (warp tile 32x48)
    int b  = blockIdx.z;
    int m0 = blockIdx.y * GBM;
    int n0 = blockIdx.x * GBN;

    const char* gA = (const char*)(g_Wh + ((size_t)b*PACK + m0)*LL);
    const char* gB = (const char*)(g_BT + ((size_t)b*DD   + n0)*LL);

    auto load_stage = [&](int ks) {
        uint32_t sdst = sbase + (uint32_t)(ks % NST) * STAGEB;
        size_t kbyte = (size_t)ks * 128;       // 64 fp16
#pragma unroll
        for (int i = 0; i < 4; i++) {          // A: 128 rows x 8 chunks
            int idx = tid + i*256;             // 0..1023
            int row = idx >> 3, c = idx & 7;
            const char* src = gA + (size_t)row*2048 + kbyte + c*16;
            uint32_t so = (uint32_t)(row*128 + ((c ^ (row & 7)) << 4));
            cp16(sdst + OFF_A + so, src);
        }
#pragma unroll
        for (int i = 0; i < 3; i++) {          // B: 96 rows x 8 chunks
            int idx = tid + i*256;             // 0..767
            int row = idx >> 3, c = idx & 7;
            const char* src = gB + (size_t)row*2048 + kbyte + c*16;
            uint32_t so = (uint32_t)(row*128 + ((c ^ (row & 7)) << 4));
            cp16(sdst + OFF_B + so, src);
        }
    };

    float acc[2][6][4];
#pragma unroll
    for (int i = 0; i < 2; i++)
#pragma unroll
        for (int j = 0; j < 6; j++)
#pragma unroll
            for (int k = 0; k < 4; k++) acc[i][j][k] = 0.0f;

    load_stage(0); CP_COMMIT();
    load_stage(1); CP_COMMIT();
    load_stage(2); CP_COMMIT();

    for (int ks = 0; ks < NKS; ks++) {
        if (ks < NKS - 3) CP_WAIT2(); else CP_WAIT0();
        __syncthreads();
        if (ks + 3 < NKS) { load_stage(ks + 3); CP_COMMIT(); }

        uint32_t s0 = sbase + (uint32_t)(ks % NST) * STAGEB;
#pragma unroll
        for (int kk = 0; kk < 4; kk++) {
            uint32_t ah[2][4];
#pragma unroll
            for (int mi = 0; mi < 2; mi++) {
                int row = wm*32 + mi*16 + (lane & 15);
                int c = kk*2 + (lane >> 4);
                uint32_t so = (uint32_t)(row*128 + ((c ^ (row & 7)) << 4));
                ldsm4(ah[mi][0], ah[mi][1], ah[mi][2], ah[mi][3], s0 + OFF_A + so);
            }
            uint32_t bh[6][2];
#pragma unroll
            for (int nj = 0; nj < 3; nj++) {
                int row = wn*48 + nj*16 + (lane & 15);
                int c = kk*2 + (lane >> 4);
                uint32_t so = (uint32_t)(row*128 + ((c ^ (row & 7)) << 4));
                uint32_t r0, r1, r2, r3;
                ldsm4(r0, r1, r2, r3, s0 + OFF_B + so);
                bh[2*nj][0] = r0; bh[2*nj][1] = r2;
                bh[2*nj+1][0] = r1; bh[2*nj+1][1] = r3;
            }
#pragma unroll
            for (int mi = 0; mi < 2; mi++)
#pragma unroll
                for (int ni = 0; ni < 6; ni++)
                    mma16816(acc[mi][ni], ah[mi], bh[ni]);
        }
    }

    // epilogue: scale by 1/(Z+1e-5), mirror-write (s,t) and (t,s)
#pragma unroll
    for (int mi = 0; mi < 2; mi++) {
#pragma unroll
        for (int h = 0; h < 2; h++) {
            int r = m0 + wm*32 + mi*16 + h*8 + (lane >> 2);
            if (r < NPAIR) {
                int s = g_ps[r], t = g_pt[r];
                float scale = 1.0f / (g_Z[b*PACK + r] + 1e-5f);
                float* o1 = out + ((size_t)b*ST + s*NEE + t)*DD;
                float* o2 = out + ((size_t)b*ST + t*NEE + s)*DD;
#pragma unroll
                for (int ni = 0; ni < 6; ni++) {
                    int col = n0 + wn*48 + ni*8 + (lane & 3)*2;
                    float2 v;
                    v.x = acc[mi][ni][h*2+0] * scale;
                    v.y = acc[mi][ni][h*2+1] * scale;
                    *(float2*)(o1 + col) = v;
                    *(float2*)(o2 + col) = v;
                }
            }
        }
    }
}

// ---------------- launch ----------------
extern "C" void kernel_launch(void* const* d_in, const int* in_sizes, int n_in,
                              void* d_out, int out_size) {
    const float* seq   = (const float*)d_in[0];   // [4,1024,768]
    const float* att   = (const float*)d_in[1];   // [4,12,1024,1024]
    const int*   midx  = (const int*)  d_in[2];   // [4,42,8]
    const int*   mmask = (const int*)  d_in[3];   // [4,42,8]
    float*       out   = (float*)d_out;           // [4,42,42,768]

    cudaFuncSetAttribute(fuse_kernel, cudaFuncAttributeMaxDynamicSharedMemorySize, 64512);
    cudaFuncSetAttribute(mma_gemm, cudaFuncAttributeMaxDynamicSharedMemorySize, NST*STAGEB);

    transpose_conv<<<dim3(LL/64, DD/32, BB), 256>>>(seq);
    fuse_kernel<<<dim3(LL/32, BB), 1024, 64512>>>(att, midx, mmask);
    mma_gemm<<<dim3(DD/GBN, PACK/GBM, BB), 256, NST*STAGEB>>>(out);
}

// round 8
// speedup vs baseline: 5.6191x; 1.1026x over previous
#include <cuda_runtime.h>
#include <cuda_fp16.h>
#include <cstdint>

// ---------------- problem constants ----------------
#define BB 4
#define LL 1024
#define DD 768
#define HH 12
#define NEE 42
#define MM 8
#define ST (NEE*NEE)     // 1764
#define NPAIR 903        // pairs with s<=t
#define PACK 1024        // padded packed rows (8 x 128)

// ---------------- device scratch ----------------
__device__ __half g_Wh[(size_t)BB*PACK*LL];   // packed symmetric W (fp16)
__device__ __half g_BT[(size_t)BB*DD*LL];     // seq^T (fp16) [b][d][l]
__device__ float  g_Zp[BB*32*PACK];           // per-ltile partial row sums
__device__ int    g_ps[PACK];                 // packed row -> s
__device__ int    g_pt[PACK];                 // packed row -> t

// ---------------- PTX helpers ----------------
__device__ __forceinline__ uint32_t smem_u32(const void* p) {
    uint32_t a;
    asm("{ .reg .u64 t; cvta.to.shared.u64 t, %1; cvt.u32.u64 %0, t; }" : "=r"(a) : "l"(p));
    return a;
}
__device__ __forceinline__ void cp16(uint32_t dst, const void* src) {
    asm volatile("cp.async.cg.shared.global [%0], [%1], 16;" :: "r"(dst), "l"(src));
}
#define CP_COMMIT() asm volatile("cp.async.commit_group;" ::: "memory")
#define CP_WAIT2()  asm volatile("cp.async.wait_group 2;" ::: "memory")
#define CP_WAIT0()  asm volatile("cp.async.wait_group 0;" ::: "memory")

__device__ __forceinline__ void ldsm4(uint32_t& r0, uint32_t& r1, uint32_t& r2, uint32_t& r3,
                                      uint32_t addr) {
    asm volatile("ldmatrix.sync.aligned.m8n8.x4.shared.b16 {%0,%1,%2,%3}, [%4];"
                 : "=r"(r0), "=r"(r1), "=r"(r2), "=r"(r3) : "r"(addr));
}
__device__ __forceinline__ void mma16816(float* d, const uint32_t* a, const uint32_t* b) {
    asm volatile(
        "mma.sync.aligned.m16n8k16.row.col.f32.f16.f16.f32 "
        "{%0,%1,%2,%3},{%4,%5,%6,%7},{%8,%9},{%0,%1,%2,%3};"
        : "+f"(d[0]), "+f"(d[1]), "+f"(d[2]), "+f"(d[3])
        : "r"(a[0]), "r"(a[1]), "r"(a[2]), "r"(a[3]), "r"(b[0]), "r"(b[1]));
}

// ---------------- Kernel P: merged prep ----------------
// blocks 0..127   : fused ent_att + Gram + fp16 W + Z partials   (launched first)
// blocks 128..511 : seq transpose+convert -> g_BT                (fills idle slots)
// 1024 threads, dyn smem 64512 B
__global__ void __launch_bounds__(1024) prep_kernel(const float* __restrict__ seq,
                                                    const float* __restrict__ att,
                                                    const int* __restrict__ midx,
                                                    const int* __restrict__ mmask) {
    extern __shared__ char sm[];
    int tid = threadIdx.x;
    int lane = tid & 31, warp = tid >> 5;

    if (blockIdx.x >= 128) {
        // ---------- transpose path ----------
        int tb = blockIdx.x - 128;           // 0..383
        if (tb == 0) {
            for (int i = tid; i < ST; i += 1024) {
                int s = i / NEE, tt = i % NEE;
                if (s <= tt) {
                    int r = s*NEE - s*(s+1)/2 + tt;
                    g_ps[r] = s; g_pt[r] = tt;
                }
            }
        }
        int b = tb / 96, rem = tb % 96;
        int l0 = (rem & 15) * 64, d0 = (rem >> 4) * 128;
        float (*ts)[129] = (float(*)[129])sm;   // 64 x 129 floats = 33 KB

#pragma unroll
        for (int p = 0; p < 8; p++) {
            int l = (tid >> 7) + p*8;            // 0..63
            int d = tid & 127;
            ts[l][d] = seq[((size_t)b*LL + l0 + l)*DD + d0 + d];
        }
        __syncthreads();
#pragma unroll
        for (int q = 0; q < 4; q++) {
            int d = warp + q*32;                 // 0..127
            __half2 v = __floats2half2_rn(ts[2*lane][d], ts[2*lane+1][d]);
            *(__half2*)(&g_BT[((size_t)b*DD + d0 + d)*LL + l0 + 2*lane]) = v;
        }
        return;
    }

    // ---------- fuse path ----------
    float* As = (float*)sm;                 // [h*NEE+e][32] = 64512 B
    __shared__ int   sidx[NEE*MM];
    __shared__ int   scnt[NEE];
    __shared__ float sinv[NEE];

    int fb = blockIdx.x;                    // 0..127
    int b = fb >> 5, j = fb & 31, l0 = j * 32;

    if (tid < NEE) {
        int e = tid, k = 0;
        const int* ip = midx  + (b*NEE + e)*MM;
        const int* mp = mmask + (b*NEE + e)*MM;
#pragma unroll
        for (int m = 0; m < MM; m++) {
            int i = ip[m] + 1;
            if (mp[m] > 0 && i < LL) sidx[e*MM + (k++)] = i;
        }
        scnt[e] = k;
        sinv[e] = 1.0f / (float)(k > 0 ? k : 1);
        for (int m = k; m < MM; m++) sidx[e*MM + m] = 0;   // pad -> L2-hot row 0
    }
    __syncthreads();

    // gather: one warp per (h,e); fixed-8 unrolled predicated loads (MLP=8)
    const float* ab0 = att + (size_t)b * HH * LL * LL + l0 + lane;
    for (int he = warp; he < HH*NEE; he += 32) {
        int h = he / NEE, e = he % NEE;
        const float* ab = ab0 + (size_t)h * LL * LL;
        int c = scnt[e];
        float s = 0.0f;
#pragma unroll
        for (int m = 0; m < MM; m++) {
            float v = ab[(size_t)sidx[e*MM + m] * LL];
            s += (m < c) ? v : 0.0f;
        }
        As[he*32 + lane] = s * sinv[e];
    }
    __syncthreads();

    // Gram: lane = l, warp covers t = s+warp (+32)
    const float invH = 1.0f / (float)HH;
    float* zp = g_Zp + (b*32 + j)*PACK;
    for (int s = 0; s < NEE; s++) {
        int t1 = s + warp;
        if (t1 < NEE) {
            float as[HH];
#pragma unroll
            for (int h = 0; h < HH; h++)
                as[h] = As[(h*NEE + s)*32 + lane];
            int rbase = s*NEE - s*(s+1)/2;
            {
                float acc = 0.0f;
#pragma unroll
                for (int h = 0; h < HH; h++)
                    acc = fmaf(as[h], As[(h*NEE + t1)*32 + lane], acc);
                float w = acc * invH;
                g_Wh[((size_t)b*PACK + rbase + t1)*LL + l0 + lane] = __float2half(w);
                float zs = w;
#pragma unroll
                for (int off = 16; off > 0; off >>= 1)
                    zs += __shfl_xor_sync(0xffffffffu, zs, off);
                if (lane == 0) zp[rbase + t1] = zs;
            }
            int t2 = t1 + 32;
            if (t2 < NEE) {
                float acc = 0.0f;
#pragma unroll
                for (int h = 0; h < HH; h++)
                    acc = fmaf(as[h], As[(h*NEE + t2)*32 + lane], acc);
                float w = acc * invH;
                g_Wh[((size_t)b*PACK + rbase + t2)*LL + l0 + lane] = __float2half(w);
                float zs = w;
#pragma unroll
                for (int off = 16; off > 0; off >>= 1)
                    zs += __shfl_xor_sync(0xffffffffu, zs, off);
                if (lane == 0) zp[rbase + t2] = zs;
            }
        }
    }
}

// ---------------- Kernel C: fp16 HMMA GEMM + symmetric epilogue ----------------
// per batch: C[1024(903),768] = Wp[.,1024] @ seq[1024,768]; tiles 128x96, mirror writes
#define GBM 128
#define GBN 96
#define NST 4
#define OFF_A 0
#define OFF_B 16384
#define STAGEB 28672               // A 16KB + B 12KB
#define NKS 16                     // 1024 / 64

__global__ void __launch_bounds__(256, 2) mma_gemm(float* __restrict__ out) {
    extern __shared__ __align__(1024) char smc[];
    uint32_t sbase = smem_u32(smc);

    int tid = threadIdx.x, lane = tid & 31, wid = tid >> 5;
    int wm = wid & 3, wn = wid >> 2;          // 4 x 2 warp grid (warp tile 32x48)
    int b  = blockIdx.z;
    int m0 = blockIdx.y * GBM;
    int n0 = blockIdx.x * GBN;

    const char* gA = (const char*)(g_Wh + ((size_t)b*PACK + m0)*LL);
    const char* gB = (const char*)(g_BT + ((size_t)b*DD   + n0)*LL);

    auto load_stage = [&](int ks) {
        uint32_t sdst = sbase + (uint32_t)(ks % NST) * STAGEB;
        size_t kbyte = (size_t)ks * 128;       // 64 fp16
#pragma unroll
        for (int i = 0; i < 4; i++) {          // A: 128 rows x 8 chunks
            int idx = tid + i*256;             // 0..1023
            int row = idx >> 3, c = idx & 7;
            const char* src = gA + (size_t)row*2048 + kbyte + c*16;
            uint32_t so = (uint32_t)(row*128 + ((c ^ (row & 7)) << 4));
            cp16(sdst + OFF_A + so, src);
        }
#pragma unroll
        for (int i = 0; i < 3; i++) {          // B: 96 rows x 8 chunks
            int idx = tid + i*256;             // 0..767
            int row = idx >> 3, c = idx & 7;
            const char* src = gB + (size_t)row*2048 + kbyte + c*16;
            uint32_t so = (uint32_t)(row*128 + ((c ^ (row & 7)) << 4));
            cp16(sdst + OFF_B + so, src);
        }
    };

    load_stage(0); CP_COMMIT();
    load_stage(1); CP_COMMIT();
    load_stage(2); CP_COMMIT();

    // Z reduction overlapped with pipeline warm-up:
    // the 4 threads sharing row r (lane&3) each sum 8 of 32 partials, then shfl-combine.
    float zsc[2][2];
#pragma unroll
    for (int mi = 0; mi < 2; mi++)
#pragma unroll
        for (int h = 0; h < 2; h++) {
            int r = m0 + wm*32 + mi*16 + h*8 + (lane >> 2);
            const float* zp = g_Zp + b*32*PACK + (lane & 3)*8*PACK + r;
            float z = 0.0f;
#pragma unroll
            for (int q = 0; q < 8; q++) z += zp[q*PACK];
            z += __shfl_xor_sync(0xffffffffu, z, 1);
            z += __shfl_xor_sync(0xffffffffu, z, 2);
            zsc[mi][h] = 1.0f / (z + 1e-5f);
        }

    float acc[2][6][4];
#pragma unroll
    for (int i = 0; i < 2; i++)
#pragma unroll
        for (int j = 0; j < 6; j++)
#pragma unroll
            for (int k = 0; k < 4; k++) acc[i][j][k] = 0.0f;

    for (int ks = 0; ks < NKS; ks++) {
        if (ks < NKS - 3) CP_WAIT2(); else CP_WAIT0();
        __syncthreads();
        if (ks + 3 < NKS) { load_stage(ks + 3); CP_COMMIT(); }

        uint32_t s0 = sbase + (uint32_t)(ks % NST) * STAGEB;
#pragma unroll
        for (int kk = 0; kk < 4; kk++) {
            uint32_t ah[2][4];
#pragma unroll
            for (int mi = 0; mi < 2; mi++) {
                int row = wm*32 + mi*16 + (lane & 15);
                int c = kk*2 + (lane >> 4);
                uint32_t so = (uint32_t)(row*128 + ((c ^ (row & 7)) << 4));
                ldsm4(ah[mi][0], ah[mi][1], ah[mi][2], ah[mi][3], s0 + OFF_A + so);
            }
            uint32_t bh[6][2];
#pragma unroll
            for (int nj = 0; nj < 3; nj++) {
                int row = wn*48 + nj*16 + (lane & 15);
                int c = kk*2 + (lane >> 4);
                uint32_t so = (uint32_t)(row*128 + ((c ^ (row & 7)) << 4));
                uint32_t r0, r1, r2, r3;
                ldsm4(r0, r1, r2, r3, s0 + OFF_B + so);
                bh[2*nj][0] = r0; bh[2*nj][1] = r2;
                bh[2*nj+1][0] = r1; bh[2*nj+1][1] = r3;
            }
#pragma unroll
            for (int mi = 0; mi < 2; mi++)
#pragma unroll
                for (int ni = 0; ni < 6; ni++)
                    mma16816(acc[mi][ni], ah[mi], bh[ni]);
        }
    }

    // epilogue: scale by precomputed 1/(Z+1e-5), mirror-write (s,t) and (t,s)
#pragma unroll
    for (int mi = 0; mi < 2; mi++) {
#pragma unroll
        for (int h = 0; h < 2; h++) {
            int r = m0 + wm*32 + mi*16 + h*8 + (lane >> 2);
            if (r < NPAIR) {
                int s = g_ps[r], t = g_pt[r];
                float scale = zsc[mi][h];
                float* o1 = out + ((size_t)b*ST + s*NEE + t)*DD;
                float* o2 = out + ((size_t)b*ST + t*NEE + s)*DD;
#pragma unroll
                for (int ni = 0; ni < 6; ni++) {
                    int col = n0 + wn*48 + ni*8 + (lane & 3)*2;
                    float2 v;
                    v.x = acc[mi][ni][h*2+0] * scale;
                    v.y = acc[mi][ni][h*2+1] * scale;
                    *(float2*)(o1 + col) = v;
                    *(float2*)(o2 + col) = v;
                }
            }
        }
    }
}

// ---------------- launch ----------------
extern "C" void kernel_launch(void* const* d_in, const int* in_sizes, int n_in,
                              void* d_out, int out_size) {
    const float* seq   = (const float*)d_in[0];   // [4,1024,768]
    const float* att   = (const float*)d_in[1];   // [4,12,1024,1024]
    const int*   midx  = (const int*)  d_in[2];   // [4,42,8]
    const int*   mmask = (const int*)  d_in[3];   // [4,42,8]
    float*       out   = (float*)d_out;           // [4,42,42,768]

    cudaFuncSetAttribute(prep_kernel, cudaFuncAttributeMaxDynamicSharedMemorySize, 64512);
    cudaFuncSetAttribute(mma_gemm, cudaFuncAttributeMaxDynamicSharedMemorySize, NST*STAGEB);

    prep_kernel<<<512, 1024, 64512>>>(seq, att, midx, mmask);
    mma_gemm<<<dim3(DD/GBN, PACK/GBM, BB), 256, NST*STAGEB>>>(out);
}